// round 1
// baseline (speedup 1.0000x reference)
#include <cuda_runtime.h>
#include <cstdint>

#define DMODEL 2048
#define NB 144          // 64 (s1) + 64 (s2) + 16 (qg)
#define BM 128
#define BK 16
#define TOK 64

// Scratch: S[N][144] = [s1 | s2 | qg] per token (device global, no alloc)
__device__ float g_S[16384 * NB];

// ---------------------------------------------------------------------------
// Kernel 1: fused skinny GEMM  S = x @ [W1|W2|Wg]^T   (fp32, packed f32x2 FMA)
// ---------------------------------------------------------------------------
__global__ __launch_bounds__(256, 1) void pk_gemm(
    const float* __restrict__ x, const float* __restrict__ W1,
    const float* __restrict__ W2, const float* __restrict__ Wg) {
  __shared__ __align__(16) float  a_s[BK][BM + 2];     // x tile, k-major transposed
  __shared__ __align__(16) float2 b_s[BK][NB + 1];     // W tile, duplicated pairs (pad kills STS conflicts)

  const int tid = threadIdx.x;
  const int tx = tid & 15;          // n dim
  const int ty = tid >> 4;          // m dim
  const int m_base = blockIdx.x * BM;
  const int n0 = tx * 9;            // 16*9 = 144 cols
  const int m0 = ty * 8;            // 16*8 = 128 rows

  unsigned long long acc[4][9];     // 4 m-pairs x 9 n, packed f32x2
#pragma unroll
  for (int p = 0; p < 4; p++)
#pragma unroll
    for (int j = 0; j < 9; j++) acc[p][j] = 0ull;

  // A stage: thread loads row am, 8 floats at k-offset ak0
  const int am = tid >> 1;
  const int ak0 = (tid & 1) * 8;
  const float* a_src = x + (size_t)(m_base + am) * DMODEL + ak0;

  float4 a_r0 = *(const float4*)(a_src);
  float4 a_r1 = *(const float4*)(a_src + 4);
  float w_r[9];
#pragma unroll
  for (int j = 0; j < 9; j++) {
    int i = tid + 256 * j;
    int n = i >> 4, kk = i & 15;
    const float* wr = (n < 64) ? (W1 + (size_t)n * DMODEL)
                   : (n < 128) ? (W2 + (size_t)(n - 64) * DMODEL)
                               : (Wg + (size_t)(n - 128) * DMODEL);
    w_r[j] = wr[kk];
  }

  const int KT = DMODEL / BK;   // 128
  for (int kt = 0; kt < KT; kt++) {
    // commit staged regs to smem
#pragma unroll
    for (int u = 0; u < 4; u++) a_s[ak0 + u][am] = ((const float*)&a_r0)[u];
#pragma unroll
    for (int u = 0; u < 4; u++) a_s[ak0 + 4 + u][am] = ((const float*)&a_r1)[u];
#pragma unroll
    for (int j = 0; j < 9; j++) {
      int i = tid + 256 * j;
      int n = i >> 4, kk = i & 15;
      b_s[kk][n] = make_float2(w_r[j], w_r[j]);
    }
    __syncthreads();

    // prefetch next tile into regs (hides gmem latency under compute)
    if (kt + 1 < KT) {
      const float* asrc = a_src + (size_t)(kt + 1) * BK;
      a_r0 = *(const float4*)(asrc);
      a_r1 = *(const float4*)(asrc + 4);
      const int k0n = (kt + 1) * BK;
#pragma unroll
      for (int j = 0; j < 9; j++) {
        int i = tid + 256 * j;
        int n = i >> 4, kk = i & 15;
        const float* wr = (n < 64) ? (W1 + (size_t)n * DMODEL)
                       : (n < 128) ? (W2 + (size_t)(n - 64) * DMODEL)
                                   : (Wg + (size_t)(n - 128) * DMODEL);
        w_r[j] = wr[k0n + kk];
      }
    }

    // compute: 16 k-steps x 36 packed FMAs
#pragma unroll
    for (int kk = 0; kk < BK; kk++) {
      unsigned long long a2[4], b2[9];
#pragma unroll
      for (int p = 0; p < 4; p++)
        a2[p] = *(const unsigned long long*)&a_s[kk][m0 + 2 * p];
#pragma unroll
      for (int j = 0; j < 9; j++)
        b2[j] = *(const unsigned long long*)&b_s[kk][n0 + j];
#pragma unroll
      for (int p = 0; p < 4; p++)
#pragma unroll
        for (int j = 0; j < 9; j++)
          asm("fma.rn.f32x2 %0, %1, %2, %0;"
              : "+l"(acc[p][j]) : "l"(a2[p]), "l"(b2[j]));
    }
    __syncthreads();
  }

  // epilogue: unpack pairs, store S
#pragma unroll
  for (int p = 0; p < 4; p++) {
    const int mg = m_base + m0 + 2 * p;
#pragma unroll
    for (int j = 0; j < 9; j++) {
      unsigned long long v = acc[p][j];
      g_S[(size_t)mg * NB + n0 + j] = __uint_as_float((unsigned)v);
      g_S[(size_t)(mg + 1) * NB + n0 + j] = __uint_as_float((unsigned)(v >> 32));
    }
  }
}

// ---------------------------------------------------------------------------
// Kernel 2: top-8 (product-key), low-rank gate, softmax
// ---------------------------------------------------------------------------
// Tie-aware sorted-list insert: (value desc, index asc) == jax.lax.top_k order
__device__ __forceinline__ void insert8(float v, int idx, float* vals, int* idxs) {
  if (v < vals[7] || (v == vals[7] && idx >= idxs[7])) return;
  int p = 7;
  while (p > 0 && (v > vals[p - 1] || (v == vals[p - 1] && idx < idxs[p - 1]))) {
    vals[p] = vals[p - 1]; idxs[p] = idxs[p - 1]; --p;
  }
  vals[p] = v; idxs[p] = idx;
}

__global__ __launch_bounds__(256, 1) void pk_topk(
    const float* __restrict__ G,
    float* __restrict__ out_idx, float* __restrict__ out_w) {
  __shared__ __align__(16) float s_s[TOK][NB + 4];
  const int tid = threadIdx.x;
  const int t0 = blockIdx.x * TOK;

  for (int i = tid; i < TOK * (NB / 4); i += 256) {
    int m = i / (NB / 4), c = i % (NB / 4);
    *(float4*)&s_s[m][c * 4] = *(const float4*)(g_S + (size_t)(t0 + m) * NB + c * 4);
  }
  __syncthreads();

  if (tid < TOK) {
    const float* r = s_s[tid];
    float v1[8], v2[8], cv[8];
    int i1[8], i2[8], ci[8];
#pragma unroll
    for (int t = 0; t < 8; t++) {
      v1[t] = v2[t] = cv[t] = -3.4e38f;
      i1[t] = i2[t] = ci[t] = 0x7fffffff;
    }
    for (int a = 0; a < 64; a++) insert8(r[a], a, v1, i1);
    for (int b = 0; b < 64; b++) insert8(r[64 + b], b, v2, i2);
    // top-8 pairs are provably within top8(s1) x top8(s2)
    for (int ai = 0; ai < 8; ai++)
      for (int bi = 0; bi < 8; bi++)
        insert8(v1[ai] + v2[bi], i1[ai] * 64 + i2[bi], cv, ci);

    float comb[8];
    for (int t = 0; t < 8; t++) {
      const float* grow = G + (size_t)ci[t] * 16;
      float g = 0.f;
#pragma unroll
      for (int u = 0; u < 16; u++) g += r[128 + u] * grow[u];
      comb[t] = cv[t] + g;
    }
    float mx = comb[0];
    for (int t = 1; t < 8; t++) mx = fmaxf(mx, comb[t]);
    float e[8], sum = 0.f;
    for (int t = 0; t < 8; t++) { e[t] = expf(comb[t] - mx); sum += e[t]; }
    const float inv = 1.f / sum;
    const int gm = t0 + tid;
    for (int t = 0; t < 8; t++) {
      out_idx[gm * 8 + t] = (float)ci[t];
      out_w[gm * 8 + t] = e[t] * inv;
    }
  }
}

// ---------------------------------------------------------------------------
// Kernel 3: expand select_scores[i, a*64+b] = s1[i,a] + s2[i,b]  (256 MB write)
// ---------------------------------------------------------------------------
__global__ __launch_bounds__(256, 1) void pk_expand(float4* __restrict__ out) {
  const int i = blockIdx.x * 256 + threadIdx.x;   // over Ntok*1024 float4s
  const int m = i >> 10;
  const int r = i & 1023;
  const int a = r >> 4;
  const int b4 = r & 15;
  const float* row = g_S + (size_t)m * NB;
  const float s1 = __ldg(row + a);
  const float4 s2 = *(const float4*)(row + 64 + b4 * 4);
  out[i] = make_float4(s1 + s2.x, s1 + s2.y, s1 + s2.z, s1 + s2.w);
}

// ---------------------------------------------------------------------------
extern "C" void kernel_launch(void* const* d_in, const int* in_sizes, int n_in,
                              void* d_out, int out_size) {
  const float* x  = (const float*)d_in[0];
  const float* W1 = (const float*)d_in[1];
  const float* W2 = (const float*)d_in[2];
  const float* Wg = (const float*)d_in[3];
  const float* G  = (const float*)d_in[4];
  float* out = (float*)d_out;

  const int Ntok = in_sizes[0] / DMODEL;   // 16384

  // Output layout (reference tuple, flattened & concatenated, float32):
  //   [0, N*8)        topk_idx (as float)
  //   [N*8, N*16)     topk_weights
  //   [N*16, ...)     select_scores [N, 4096]
  float* out_idx = out;
  float* out_w   = out + (size_t)Ntok * 8;
  float* out_sc  = out + (size_t)Ntok * 16;

  pk_gemm<<<Ntok / BM, 256>>>(x, W1, W2, Wg);
  pk_topk<<<Ntok / TOK, 256>>>(G, out_idx, out_w);
  pk_expand<<<Ntok * 4, 256>>>((float4*)out_sc);
}